// round 3
// baseline (speedup 1.0000x reference)
#include <cuda_runtime.h>
#include <math.h>

#define BATCH 8
#define HH 720
#define WW 1280
#define HW (HH * WW)
#define NPIX (BATCH * HW)

// Packed accumulator: (cnt, ox, oy, pad). 16B aligned for red.global.add.v4.f32.
__device__ float4 g_acc[NPIX];

// ---------------------------------------------------------------------------
// Kernel 1: zero the accumulator plane. 4 float4 per thread per iteration.
// NPIX = 7,372,800; / 4 = 1,843,200 chunks of 4 float4.
// ---------------------------------------------------------------------------
__global__ void zero_kernel() {
    const int nchunk = NPIX / 4;  // each chunk = 4 float4 = 4 pixels
    float4 z = make_float4(0.f, 0.f, 0.f, 0.f);
    int stride = gridDim.x * blockDim.x;
    for (int k = blockIdx.x * blockDim.x + threadIdx.x; k < nchunk; k += stride) {
        float4* p = &g_acc[k * 4];
        p[0] = z; p[1] = z; p[2] = z; p[3] = z;
    }
}

// ---------------------------------------------------------------------------
// Kernel 2: scatter. One thread per source pixel; 4 vector reductions
// (one per bilinear corner).
// ---------------------------------------------------------------------------
__device__ __forceinline__ void red_add_v4(float4* addr, float a, float b, float c) {
    asm volatile(
        "red.global.add.v4.f32 [%0], {%1, %2, %3, %4};"
        :: "l"(addr), "f"(a), "f"(b), "f"(c), "f"(0.0f)
        : "memory");
}

__global__ void scatter_kernel(const float* __restrict__ flow,
                               const float* __restrict__ depth) {
    int i = blockIdx.x * blockDim.x + threadIdx.x;
    if (i >= NPIX) return;

    int b = i / HW;
    int p = i - b * HW;
    int y = p / WW;
    int x = p - y * WW;

    const float* fbase = flow + (size_t)b * 2 * HW;
    float fx = fbase[p];
    float fy = fbase[HW + p];
    float d  = depth[i];

    float x2 = (float)x + fx;
    float y2 = (float)y + fy;

    if (!(x2 >= 0.f && x2 <= (float)(WW - 1) &&
          y2 >= 0.f && y2 <= (float)(HH - 1)))
        return;

    int xL = (int)floorf(x2);
    int yT = (int)floorf(y2);
    int xR = min(xL + 1, WW - 1);
    int yB = min(yT + 1, HH - 1);

    float wx = -fx * d;
    float wy = -fy * d;

    int base = b * HW;
    int rT = base + yT * WW;
    int rB = base + yB * WW;

    red_add_v4(&g_acc[rT + xL], d, wx, wy);
    red_add_v4(&g_acc[rT + xR], d, wx, wy);
    red_add_v4(&g_acc[rB + xL], d, wx, wy);
    red_add_v4(&g_acc[rB + xR], d, wx, wy);
}

// ---------------------------------------------------------------------------
// Kernel 3: normalize + write (B, 2, H, W). 4 pixels per thread:
// 4x LDG.128 in, 2x STG.128 out (one float4 per output plane).
// ---------------------------------------------------------------------------
__global__ void normalize_kernel(float* __restrict__ out) {
    int t = blockIdx.x * blockDim.x + threadIdx.x;   // one per 4-pixel group
    const int ngroup = NPIX / 4;
    if (t >= ngroup) return;

    int i = t * 4;           // first pixel of the group
    int b = i / HW;          // HW divisible by 4, group never crosses batch
    int p = i - b * HW;

    float4 ox4, oy4;
    float* oxp = &ox4.x;
    float* oyp = &oy4.x;
#pragma unroll
    for (int j = 0; j < 4; j++) {
        float4 a = g_acc[i + j];
        float ox = 0.f, oy = 0.f;
        if (a.x > 0.f) {
            float inv = 1.f / a.x;
            ox = a.y * inv;
            oy = a.z * inv;
        }
        oxp[j] = ox;
        oyp[j] = oy;
    }

    float* obase = out + (size_t)b * 2 * HW;
    *reinterpret_cast<float4*>(obase + p)      = ox4;
    *reinterpret_cast<float4*>(obase + HW + p) = oy4;
}

extern "C" void kernel_launch(void* const* d_in, const int* in_sizes, int n_in,
                              void* d_out, int out_size) {
    const float* flow  = (const float*)d_in[0];   // (B, 2, H, W)
    const float* depth = (const float*)d_in[1];   // (B, 1, H, W)
    float* out = (float*)d_out;                   // (B, 2, H, W)

    (void)in_sizes; (void)n_in; (void)out_size;

    const int threads = 256;

    zero_kernel<<<2960, threads>>>();

    int blocks = (NPIX + threads - 1) / threads;
    scatter_kernel<<<blocks, threads>>>(flow, depth);

    int nblocks = (NPIX / 4 + threads - 1) / threads;
    normalize_kernel<<<nblocks, threads>>>(out);
}

// round 4
// speedup vs baseline: 1.1694x; 1.1694x over previous
#include <cuda_runtime.h>
#include <math.h>

#define BATCH 8
#define HH 720
#define WW 1280
#define HW (HH * WW)
#define NPIX (BATCH * HW)

// Packed accumulator: (cnt, ox, oy, pad). 16B aligned for red.global.add.v4.f32.
__device__ float4 g_acc[NPIX];

// ---------------------------------------------------------------------------
// Kernel 1: zero the accumulator plane. One float4 per thread per iteration
// (warp-contiguous 512B per STG.128 wavefront group — fully coalesced).
// ---------------------------------------------------------------------------
__global__ void zero_kernel() {
    float4 z = make_float4(0.f, 0.f, 0.f, 0.f);
    int stride = gridDim.x * blockDim.x;
    for (int k = blockIdx.x * blockDim.x + threadIdx.x; k < NPIX; k += stride) {
        g_acc[k] = z;
    }
}

// ---------------------------------------------------------------------------
// Kernel 2: scatter. One thread per source pixel; 4 vector reductions
// (one per bilinear corner).
// ---------------------------------------------------------------------------
__device__ __forceinline__ void red_add_v4(float4* addr, float a, float b, float c) {
    asm volatile(
        "red.global.add.v4.f32 [%0], {%1, %2, %3, %4};"
        :: "l"(addr), "f"(a), "f"(b), "f"(c), "f"(0.0f)
        : "memory");
}

__global__ void scatter_kernel(const float* __restrict__ flow,
                               const float* __restrict__ depth) {
    int i = blockIdx.x * blockDim.x + threadIdx.x;
    if (i >= NPIX) return;

    int b = i / HW;
    int p = i - b * HW;
    int y = p / WW;
    int x = p - y * WW;

    const float* fbase = flow + (size_t)b * 2 * HW;
    float fx = fbase[p];
    float fy = fbase[HW + p];
    float d  = depth[i];

    float x2 = (float)x + fx;
    float y2 = (float)y + fy;

    if (!(x2 >= 0.f && x2 <= (float)(WW - 1) &&
          y2 >= 0.f && y2 <= (float)(HH - 1)))
        return;

    int xL = (int)floorf(x2);
    int yT = (int)floorf(y2);
    int xR = min(xL + 1, WW - 1);
    int yB = min(yT + 1, HH - 1);

    float wx = -fx * d;
    float wy = -fy * d;

    int base = b * HW;
    int rT = base + yT * WW;
    int rB = base + yB * WW;

    red_add_v4(&g_acc[rT + xL], d, wx, wy);
    red_add_v4(&g_acc[rT + xR], d, wx, wy);
    red_add_v4(&g_acc[rB + xL], d, wx, wy);
    red_add_v4(&g_acc[rB + xR], d, wx, wy);
}

// ---------------------------------------------------------------------------
// Kernel 3: normalize + write (B, 2, H, W). Thread <-> pixel identity mapping
// (coalesced LDG.128 + coalesced scalar STG.32 to each plane). Grid-stride
// with 2 independent iterations in flight for MLP.
// ---------------------------------------------------------------------------
__global__ void normalize_kernel(float* __restrict__ out) {
    int tid = blockIdx.x * blockDim.x + threadIdx.x;
    int stride = gridDim.x * blockDim.x;          // = NPIX/2 exactly

    int i0 = tid;
    int i1 = tid + stride;

    // Two independent loads in flight.
    float4 a0 = g_acc[i0];
    float4 a1 = g_acc[i1];

    float ox0 = 0.f, oy0 = 0.f;
    if (a0.x > 0.f) { float inv = 1.f / a0.x; ox0 = a0.y * inv; oy0 = a0.z * inv; }
    float ox1 = 0.f, oy1 = 0.f;
    if (a1.x > 0.f) { float inv = 1.f / a1.x; ox1 = a1.y * inv; oy1 = a1.z * inv; }

    int b0 = i0 / HW, p0 = i0 - b0 * HW;
    int b1 = i1 / HW, p1 = i1 - b1 * HW;

    float* ob0 = out + (size_t)b0 * 2 * HW;
    float* ob1 = out + (size_t)b1 * 2 * HW;
    ob0[p0]      = ox0;
    ob0[HW + p0] = oy0;
    ob1[p1]      = ox1;
    ob1[HW + p1] = oy1;
}

extern "C" void kernel_launch(void* const* d_in, const int* in_sizes, int n_in,
                              void* d_out, int out_size) {
    const float* flow  = (const float*)d_in[0];   // (B, 2, H, W)
    const float* depth = (const float*)d_in[1];   // (B, 1, H, W)
    float* out = (float*)d_out;                   // (B, 2, H, W)

    (void)in_sizes; (void)n_in; (void)out_size;

    const int threads = 256;

    zero_kernel<<<1480, threads>>>();

    int blocks = (NPIX + threads - 1) / threads;
    scatter_kernel<<<blocks, threads>>>(flow, depth);

    // Each thread handles 2 pixels: i and i + NPIX/2 (NPIX even).
    int nblocks = (NPIX / 2) / threads;           // 7372800/2/256 = 14400
    normalize_kernel<<<nblocks, threads>>>(out);
}